// round 2
// baseline (speedup 1.0000x reference)
#include <cuda_runtime.h>
#include <math.h>

// Problem constants (fixed by reference setup_inputs)
#define NN      8192          // nodes per graph
#define NT      16384         // stacked nodes (2 graphs)
#define DF      128           // feature dim
#define EE      131072        // edges per graph
#define GB      64            // graphs per batch
#define GNODES  128           // nodes per graph-block (NN/GB)
#define PAD     132           // smem row pad (floats), 16B-aligned, conflict-breaking

// ---------------- scratch (static device globals; no allocation) -------------
__device__ float g_A  [(size_t)NT * 512];   // X @ W1_top
__device__ float g_Cb [(size_t)NT * 512];   // X @ W1_bot + mb1
__device__ float g_H  [(size_t)NT * 512];   // sum_e relu(A[src]+C[tgt])
__device__ float g_U  [(size_t)NT * 512];   // [messages(256) | att(128) | x(128)]
__device__ float g_H1 [(size_t)NT * 512];
__device__ float g_H2 [(size_t)NT * 256];
__device__ float g_XS [(size_t)NT * DF];    // stacked [x1; x2]
__device__ float g_P1 [(size_t)GB * GNODES * GNODES];   // row-softmax probs  [g][i][j]
__device__ float g_P2 [(size_t)GB * GNODES * GNODES];   // col-softmax probs, transposed [g][j][i]
__device__ int   g_deg[NT];
__device__ int   g_off[NT];
__device__ int   g_cur[NT];
__device__ int   g_srcSorted[2 * EE];

// ---------------- small prep kernels -----------------------------------------
__global__ void copy_x_kernel(const float* __restrict__ x1, const float* __restrict__ x2) {
    int idx = blockIdx.x * 256 + threadIdx.x;
    if (idx >= NT * DF) return;
    int n = idx >> 7;
    int d = idx & 127;
    float v = (n < NN) ? x1[idx] : x2[idx - (size_t)NN * DF];
    g_XS[idx] = v;
    g_U[(size_t)n * 512 + 384 + d] = v;
}

__global__ void hist_kernel(const int* __restrict__ ei, int nodeOff) {
    int e = blockIdx.x * 256 + threadIdx.x;
    if (e < EE) atomicAdd(&g_deg[nodeOff + ei[e]], 1);
}

__global__ void scan_kernel() {
    __shared__ int ssum[1024];
    int t = threadIdx.x;
    int base = t * 16;
    int loc[16];
    int s = 0;
#pragma unroll
    for (int i = 0; i < 16; i++) { loc[i] = g_deg[base + i]; s += loc[i]; }
    ssum[t] = s;
    __syncthreads();
    for (int d = 1; d < 1024; d <<= 1) {
        int v = (t >= d) ? ssum[t - d] : 0;
        __syncthreads();
        ssum[t] += v;
        __syncthreads();
    }
    int ex = (t > 0) ? ssum[t - 1] : 0;
#pragma unroll
    for (int i = 0; i < 16; i++) {
        g_off[base + i] = ex;
        g_cur[base + i] = ex;
        ex += loc[i];
    }
}

__global__ void scatter_kernel(const int* __restrict__ ei, int nodeOff) {
    int e = blockIdx.x * 256 + threadIdx.x;
    if (e < EE) {
        int tgt = ei[e];
        int src = ei[EE + e];
        int p = atomicAdd(&g_cur[nodeOff + tgt], 1);
        g_srcSorted[p] = nodeOff + src;
    }
}

// One block per target node: H[t] = sum over incident edges of relu(A[src] + C[t])
__global__ void edge_acc_kernel() {
    int t = blockIdx.x;       // 0..NT-1
    int tid = threadIdx.x;    // 128 threads, 4 floats each (float4)
    const float4 c = *(const float4*)&g_Cb[(size_t)t * 512 + tid * 4];
    float4 acc = make_float4(0.f, 0.f, 0.f, 0.f);
    int beg = g_off[t];
    int dg  = g_deg[t];
    for (int e = beg; e < beg + dg; e++) {
        int s = g_srcSorted[e];
        float4 a = *(const float4*)&g_A[(size_t)s * 512 + tid * 4];
        acc.x += fmaxf(a.x + c.x, 0.f);
        acc.y += fmaxf(a.y + c.y, 0.f);
        acc.z += fmaxf(a.z + c.z, 0.f);
        acc.w += fmaxf(a.w + c.w, 0.f);
    }
    *(float4*)&g_H[(size_t)t * 512 + tid * 4] = acc;
}

// ---------------- attention: scores + softmax stats -> P1, P2T ---------------
// grid=64 blocks (one per graph), 256 threads, ~198KB dynamic smem
__global__ void att_scores(const float* __restrict__ x1, const float* __restrict__ x2,
                           float* __restrict__ P1, float* __restrict__ P2T) {
    extern __shared__ float sm[];
    float* X1T = sm;                 // [128 d][PAD] : X1T[d][i] = x1[i][d]
    float* X2T = sm + 128 * PAD;
    float* S   = sm + 2 * 128 * PAD; // [128 i][PAD j]
    __shared__ float rmax[128], rsum[128], er[128], ecinv[128], w2[128];

    int g = blockIdx.x;
    int tid = threadIdx.x;
    const float* x1g = x1 + (size_t)g * GNODES * DF;
    const float* x2g = x2 + (size_t)g * GNODES * DF;

    for (int idx = tid; idx < GNODES * DF; idx += 256) {
        int i = idx >> 7, d = idx & 127;
        X1T[d * PAD + i] = x1g[idx];
        X2T[d * PAD + i] = x2g[idx];
    }
    __syncthreads();

    // S[i][j] = sum_d x1[i][d] * x2[j][d], 8x8 register tile per thread
    int tx = tid & 15, ty = tid >> 4;
    float acc[8][8];
#pragma unroll
    for (int i = 0; i < 8; i++)
#pragma unroll
        for (int j = 0; j < 8; j++) acc[i][j] = 0.f;

    for (int d = 0; d < 128; d++) {
        float ra[8], rb[8];
        *(float4*)&ra[0] = *(const float4*)&X1T[d * PAD + ty * 8];
        *(float4*)&ra[4] = *(const float4*)&X1T[d * PAD + ty * 8 + 4];
        *(float4*)&rb[0] = *(const float4*)&X2T[d * PAD + tx * 8];
        *(float4*)&rb[4] = *(const float4*)&X2T[d * PAD + tx * 8 + 4];
#pragma unroll
        for (int i = 0; i < 8; i++)
#pragma unroll
            for (int j = 0; j < 8; j++) acc[i][j] += ra[i] * rb[j];
    }
#pragma unroll
    for (int i = 0; i < 8; i++) {
        *(float4*)&S[(ty * 8 + i) * PAD + tx * 8]     = *(float4*)&acc[i][0];
        *(float4*)&S[(ty * 8 + i) * PAD + tx * 8 + 4] = *(float4*)&acc[i][4];
    }
    __syncthreads();

    // phase 1: row maxima (threads 0..127) and column maxima (threads 128..255)
    if (tid < 128) {
        int i = tid;
        float m = -1e30f;
        for (int j = 0; j < 128; j++) m = fmaxf(m, S[i * PAD + j]);
        rmax[i] = m;
        er[i] = expf(m);
    } else {
        int j = tid - 128;
        float m = -1e30f;
        for (int i = 0; i < 128; i++) m = fmaxf(m, S[i * PAD + j]);
        ecinv[j] = expf(-m);
    }
    __syncthreads();

    // phase 2: overwrite S with exp(S - rmax[i]); accumulate row sums
    if (tid < 128) {
        int i = tid;
        float m = rmax[i];
        float s = 0.f;
        for (int j = 0; j < 128; j++) {
            float v = expf(S[i * PAD + j] - m);
            S[i * PAD + j] = v;
            s += v;
        }
        rsum[i] = s;
    }
    __syncthreads();

    // phase 3: column sums: csum[j] = ecinv[j] * sum_i Sexp[i][j] * er[i]
    if (tid >= 128) {
        int j = tid - 128;
        float s = 0.f;
        for (int i = 0; i < 128; i++) s += S[i * PAD + j] * er[i];
        float cs = s * ecinv[j];
        w2[j] = ecinv[j] / cs;
    }
    __syncthreads();

    float* P1g = P1  + (size_t)g * GNODES * GNODES;
    float* P2g = P2T + (size_t)g * GNODES * GNODES;
    for (int idx = tid; idx < GNODES * GNODES; idx += 256) {  // P1[i][j]
        int i = idx >> 7, j = idx & 127;
        P1g[idx] = S[i * PAD + j] / rsum[i];
    }
    for (int idx = tid; idx < GNODES * GNODES; idx += 256) {  // P2T[j][i]
        int j = idx >> 7, i = idx & 127;
        P2g[idx] = S[i * PAD + j] * er[i] * w2[j];
    }
}

// grid=(64,2): z=0 -> att1 = x1 - P1 @ x2 ; z=1 -> att2 = x2 - P2^T @ x1
// writes into U columns [256, 384)
__global__ void att_apply(const float* __restrict__ x1, const float* __restrict__ x2,
                          const float* __restrict__ P1, const float* __restrict__ P2T) {
    extern __shared__ float sm[];
    float* As = sm;              // [k][PAD m]  (k-major)
    float* Bs = sm + 128 * PAD;  // [k][PAD d]
    int g = blockIdx.x, z = blockIdx.y;
    const float* Ag; const float* Bg; const float* baseg; int rowBase;
    if (z == 0) {
        Ag = P1  + (size_t)g * GNODES * GNODES;  // [m=i][k=j]
        Bg = x2  + (size_t)g * GNODES * DF;      // [k=j][d]
        baseg = x1 + (size_t)g * GNODES * DF;
        rowBase = g * GNODES;
    } else {
        Ag = P2T + (size_t)g * GNODES * GNODES;  // [m=j][k=i]
        Bg = x1  + (size_t)g * GNODES * DF;      // [k=i][d]
        baseg = x2 + (size_t)g * GNODES * DF;
        rowBase = NN + g * GNODES;
    }
    int tid = threadIdx.x;
    for (int idx = tid; idx < GNODES * GNODES; idx += 256) {
        int m = idx >> 7, k = idx & 127;
        As[k * PAD + m] = Ag[idx];                 // transpose on store
        Bs[m * PAD + k] = Bg[idx];                 // here m plays role of k-row: Bs[k'][d]
    }
    __syncthreads();

    int tx = tid & 15, ty = tid >> 4;
    float acc[8][8];
#pragma unroll
    for (int i = 0; i < 8; i++)
#pragma unroll
        for (int j = 0; j < 8; j++) acc[i][j] = 0.f;

    for (int k = 0; k < 128; k++) {
        float ra[8], rb[8];
        *(float4*)&ra[0] = *(const float4*)&As[k * PAD + ty * 8];
        *(float4*)&ra[4] = *(const float4*)&As[k * PAD + ty * 8 + 4];
        *(float4*)&rb[0] = *(const float4*)&Bs[k * PAD + tx * 8];
        *(float4*)&rb[4] = *(const float4*)&Bs[k * PAD + tx * 8 + 4];
#pragma unroll
        for (int i = 0; i < 8; i++)
#pragma unroll
            for (int j = 0; j < 8; j++) acc[i][j] += ra[i] * rb[j];
    }

#pragma unroll
    for (int i = 0; i < 8; i++) {
        int m = ty * 8 + i;
#pragma unroll
        for (int j = 0; j < 8; j++) {
            int d = tx * 8 + j;
            float v = baseg[m * DF + d] - acc[i][j];
            g_U[(size_t)(rowBase + m) * 512 + 256 + d] = v;
        }
    }
}

// ---------------- generic fp32 SGEMM: C = A@W (+bias*rowscale) (+resid) (relu) -
// BM=BN=128, BK=16, 256 threads, 8x8 per thread
__global__ __launch_bounds__(256)
void sgemm(const float* __restrict__ A, int lda,
           const float* __restrict__ W, int ldw,
           const float* __restrict__ bias,
           const int*   __restrict__ degv,
           const float* __restrict__ resid, int ldr,
           float* __restrict__ C, int ldc,
           int K, int doRelu) {
    __shared__ float As[16][128];   // k-major
    __shared__ float Ws[16][128];
    const int tid = threadIdx.x;
    const int tx = tid & 15, ty = tid >> 4;
    const int brow = blockIdx.y * 128;
    const int bcol = blockIdx.x * 128;
    const float* Ab = A + (size_t)brow * lda;
    const float* Wb = W + bcol;
    const int ar = tid >> 2, ac = (tid & 3) << 2;       // A tile: rows ar, ar+64; cols ac..ac+3
    const int wk = tid >> 5, wc = (tid & 31) << 2;      // W tile: k rows wk, wk+8; cols wc..wc+3

    float acc[8][8];
#pragma unroll
    for (int i = 0; i < 8; i++)
#pragma unroll
        for (int j = 0; j < 8; j++) acc[i][j] = 0.f;

    for (int k0 = 0; k0 < K; k0 += 16) {
        float4 a0 = *(const float4*)(Ab + (size_t)ar * lda + k0 + ac);
        float4 a1 = *(const float4*)(Ab + (size_t)(ar + 64) * lda + k0 + ac);
        float4 w0 = *(const float4*)(Wb + (size_t)(k0 + wk) * ldw + wc);
        float4 w1 = *(const float4*)(Wb + (size_t)(k0 + wk + 8) * ldw + wc);
        __syncthreads();
        As[ac + 0][ar] = a0.x; As[ac + 1][ar] = a0.y; As[ac + 2][ar] = a0.z; As[ac + 3][ar] = a0.w;
        As[ac + 0][ar + 64] = a1.x; As[ac + 1][ar + 64] = a1.y; As[ac + 2][ar + 64] = a1.z; As[ac + 3][ar + 64] = a1.w;
        *(float4*)&Ws[wk][wc]     = w0;
        *(float4*)&Ws[wk + 8][wc] = w1;
        __syncthreads();
#pragma unroll
        for (int k = 0; k < 16; k++) {
            float ra[8], rb[8];
            *(float4*)&ra[0] = *(const float4*)&As[k][ty * 8];
            *(float4*)&ra[4] = *(const float4*)&As[k][ty * 8 + 4];
            *(float4*)&rb[0] = *(const float4*)&Ws[k][tx * 8];
            *(float4*)&rb[4] = *(const float4*)&Ws[k][tx * 8 + 4];
#pragma unroll
            for (int i = 0; i < 8; i++)
#pragma unroll
                for (int j = 0; j < 8; j++) acc[i][j] += ra[i] * rb[j];
        }
    }

#pragma unroll
    for (int i = 0; i < 8; i++) {
        int row = brow + ty * 8 + i;
        float rs = degv ? (float)degv[row] : 1.0f;
#pragma unroll
        for (int j = 0; j < 8; j++) {
            int col = bcol + tx * 8 + j;
            float v = acc[i][j];
            if (bias)  v += bias[col] * rs;
            if (resid) v += resid[(size_t)row * ldr + col];
            if (doRelu) v = fmaxf(v, 0.f);
            C[(size_t)row * ldc + col] = v;
        }
    }
}

// ---------------- host ---------------------------------------------------------
extern "C" void kernel_launch(void* const* d_in, const int* in_sizes, int n_in,
                              void* d_out, int out_size) {
    const float* x1  = (const float*)d_in[0];
    const int*   ei1 = (const int*)  d_in[1];
    const float* x2  = (const float*)d_in[3];
    const int*   ei2 = (const int*)  d_in[4];
    const float* mW1 = (const float*)d_in[6];
    const float* mb1 = (const float*)d_in[7];
    const float* mW2 = (const float*)d_in[8];
    const float* mb2 = (const float*)d_in[9];
    const float* uW1 = (const float*)d_in[10];
    const float* ub1 = (const float*)d_in[11];
    const float* uW2 = (const float*)d_in[12];
    const float* ub2 = (const float*)d_in[13];
    const float* uW3 = (const float*)d_in[14];
    const float* ub3 = (const float*)d_in[15];
    float* out = (float*)d_out;

    float *pA, *pC, *pH, *pU, *pH1, *pH2, *pXS, *pP1, *pP2;
    int *pdeg;
    cudaGetSymbolAddress((void**)&pA,  g_A);
    cudaGetSymbolAddress((void**)&pC,  g_Cb);
    cudaGetSymbolAddress((void**)&pH,  g_H);
    cudaGetSymbolAddress((void**)&pU,  g_U);
    cudaGetSymbolAddress((void**)&pH1, g_H1);
    cudaGetSymbolAddress((void**)&pH2, g_H2);
    cudaGetSymbolAddress((void**)&pXS, g_XS);
    cudaGetSymbolAddress((void**)&pP1, g_P1);
    cudaGetSymbolAddress((void**)&pP2, g_P2);
    cudaGetSymbolAddress((void**)&pdeg, g_deg);

    cudaMemsetAsync(pdeg, 0, NT * sizeof(int));

    copy_x_kernel<<<(NT * DF) / 256, 256>>>(x1, x2);

    hist_kernel<<<EE / 256, 256>>>(ei1, 0);
    hist_kernel<<<EE / 256, 256>>>(ei2, NN);
    scan_kernel<<<1, 1024>>>();
    scatter_kernel<<<EE / 256, 256>>>(ei1, 0);
    scatter_kernel<<<EE / 256, 256>>>(ei2, NN);

    dim3 gRows(1, NT / 128);
    // G1a: A = X @ W1_top   [NT,512] K=128
    sgemm<<<dim3(4, NT / 128), 256>>>(pXS, 128, mW1, 512,
                                      nullptr, nullptr, nullptr, 0,
                                      pA, 512, 128, 0);
    // G1b: C = X @ W1_bot + mb1
    sgemm<<<dim3(4, NT / 128), 256>>>(pXS, 128, mW1 + 128 * 512, 512,
                                      mb1, nullptr, nullptr, 0,
                                      pC, 512, 128, 0);

    edge_acc_kernel<<<NT, 128>>>();

    // G2: U[:,0:256] = H @ mW2 + deg * mb2
    sgemm<<<dim3(2, NT / 128), 256>>>(pH, 512, mW2, 256,
                                      mb2, pdeg, nullptr, 0,
                                      pU, 512, 512, 0);

    // attention
    size_t smA = (size_t)3 * 128 * PAD * sizeof(float);
    cudaFuncSetAttribute(att_scores, cudaFuncAttributeMaxDynamicSharedMemorySize, (int)smA);
    att_scores<<<GB, 256, smA>>>(x1, x2, pP1, pP2);
    size_t smB = (size_t)2 * 128 * PAD * sizeof(float);
    cudaFuncSetAttribute(att_apply, cudaFuncAttributeMaxDynamicSharedMemorySize, (int)smB);
    att_apply<<<dim3(GB, 2), 256, smB>>>(x1, x2, pP1, pP2);

    // update MLP
    sgemm<<<dim3(4, NT / 128), 256>>>(pU, 512, uW1, 512,
                                      ub1, nullptr, nullptr, 0,
                                      pH1, 512, 512, 1);
    sgemm<<<dim3(2, NT / 128), 256>>>(pH1, 512, uW2, 256,
                                      ub2, nullptr, nullptr, 0,
                                      pH2, 256, 512, 1);
    // G5: out = XS + H2 @ uW3 + ub3
    sgemm<<<dim3(1, NT / 128), 256>>>(pH2, 256, uW3, 128,
                                      ub3, nullptr, pXS, 128,
                                      out, 128, 256, 0);
}

// round 3
// speedup vs baseline: 2.3739x; 2.3739x over previous
#include <cuda_runtime.h>
#include <math.h>
#include <stdint.h>

// Problem constants (fixed by reference setup_inputs)
#define NN      8192          // nodes per graph
#define NT      16384         // stacked nodes (2 graphs)
#define DF      128           // feature dim
#define EE      131072        // edges per graph
#define GB      64            // graphs per batch
#define GNODES  128           // nodes per graph-block (NN/GB)
#define PAD     132           // smem row pad for attention kernels

// ---------------- scratch (static device globals; no allocation) -------------
__device__ float g_A  [(size_t)NT * 512];   // X @ W1_top
__device__ float g_Cb [(size_t)NT * 512];   // X @ W1_bot + mb1
__device__ float g_H  [(size_t)NT * 512];   // sum_e relu(A[src]+C[tgt])
__device__ float g_U  [(size_t)NT * 512];   // [messages(256) | att(128) | x(128)]
__device__ float g_H1 [(size_t)NT * 512];
__device__ float g_H2 [(size_t)NT * 256];
__device__ float g_XS [(size_t)NT * DF];    // stacked [x1; x2]
__device__ float g_P1 [(size_t)GB * GNODES * GNODES];   // row-softmax probs  [g][i][j]
__device__ float g_P2 [(size_t)GB * GNODES * GNODES];   // col-softmax probs, transposed [g][j][i]
__device__ int   g_deg[NT];
__device__ int   g_off[NT];
__device__ int   g_cur[NT];
__device__ int   g_srcSorted[2 * EE];

__device__ __forceinline__ float to_tf32(float x) {
    asm("cvt.rna.tf32.f32 %0, %1;" : "=f"(x) : "f"(x));
    return x;
}

__device__ __forceinline__ void mma8(float* c, const uint32_t* a, const uint32_t* b) {
    asm volatile(
        "mma.sync.aligned.m16n8k8.row.col.f32.tf32.tf32.f32 "
        "{%0,%1,%2,%3}, {%4,%5,%6,%7}, {%8,%9}, {%0,%1,%2,%3};\n"
        : "+f"(c[0]), "+f"(c[1]), "+f"(c[2]), "+f"(c[3])
        : "r"(a[0]), "r"(a[1]), "r"(a[2]), "r"(a[3]), "r"(b[0]), "r"(b[1]));
}

// ---------------- small prep kernels -----------------------------------------
__global__ void copy_x_kernel(const float* __restrict__ x1, const float* __restrict__ x2) {
    int idx = blockIdx.x * 256 + threadIdx.x;
    if (idx >= NT * DF) return;
    int n = idx >> 7;
    int d = idx & 127;
    float v = (n < NN) ? x1[idx] : x2[idx - (size_t)NN * DF];
    g_XS[idx] = v;
    g_U[(size_t)n * 512 + 384 + d] = v;
}

// both graphs in one launch
__global__ void hist_kernel(const int* __restrict__ ei1, const int* __restrict__ ei2) {
    int e = blockIdx.x * 256 + threadIdx.x;
    if (e < EE)           atomicAdd(&g_deg[ei1[e]], 1);
    else if (e < 2 * EE)  atomicAdd(&g_deg[NN + ei2[e - EE]], 1);
}

// warp-shuffle scan: 1024 threads, 16 items each
__global__ void scan_kernel() {
    __shared__ int wsum[32];
    int t = threadIdx.x;
    int lane = t & 31, wid = t >> 5;
    int base = t * 16;
    int loc[16];
    int s = 0;
#pragma unroll
    for (int i = 0; i < 16; i++) { loc[i] = g_deg[base + i]; s += loc[i]; }
    int inc = s;
#pragma unroll
    for (int d = 1; d < 32; d <<= 1) {
        int v = __shfl_up_sync(0xFFFFFFFFu, inc, d);
        if (lane >= d) inc += v;
    }
    if (lane == 31) wsum[wid] = inc;
    __syncthreads();
    if (wid == 0) {
        int v = wsum[lane];
#pragma unroll
        for (int d = 1; d < 32; d <<= 1) {
            int u = __shfl_up_sync(0xFFFFFFFFu, v, d);
            if (lane >= d) v += u;
        }
        wsum[lane] = v;
    }
    __syncthreads();
    int ex = inc - s + (wid > 0 ? wsum[wid - 1] : 0);
#pragma unroll
    for (int i = 0; i < 16; i++) {
        g_off[base + i] = ex;
        g_cur[base + i] = ex;
        ex += loc[i];
    }
}

__global__ void scatter_kernel(const int* __restrict__ ei1, const int* __restrict__ ei2) {
    int e = blockIdx.x * 256 + threadIdx.x;
    if (e < EE) {
        int tgt = ei1[e];
        int src = ei1[EE + e];
        int p = atomicAdd(&g_cur[tgt], 1);
        g_srcSorted[p] = src;
    } else if (e < 2 * EE) {
        int e2 = e - EE;
        int tgt = ei2[e2];
        int src = ei2[EE + e2];
        int p = atomicAdd(&g_cur[NN + tgt], 1);
        g_srcSorted[p] = NN + src;
    }
}

// One block per target node: H[t] = sum over incident edges of relu(A[src] + C[t])
__global__ void edge_acc_kernel() {
    int t = blockIdx.x;       // 0..NT-1
    int tid = threadIdx.x;    // 128 threads, 4 floats each (float4)
    const float4 c = *(const float4*)&g_Cb[(size_t)t * 512 + tid * 4];
    float4 acc = make_float4(0.f, 0.f, 0.f, 0.f);
    int beg = g_off[t];
    int dg  = g_deg[t];
    for (int e = beg; e < beg + dg; e++) {
        int s = g_srcSorted[e];
        float4 a = *(const float4*)&g_A[(size_t)s * 512 + tid * 4];
        acc.x += fmaxf(a.x + c.x, 0.f);
        acc.y += fmaxf(a.y + c.y, 0.f);
        acc.z += fmaxf(a.z + c.z, 0.f);
        acc.w += fmaxf(a.w + c.w, 0.f);
    }
    *(float4*)&g_H[(size_t)t * 512 + tid * 4] = acc;
}

// ---------------- attention: scores + softmax stats -> P1, P2T ---------------
__global__ void att_scores(const float* __restrict__ x1, const float* __restrict__ x2,
                           float* __restrict__ P1, float* __restrict__ P2T) {
    extern __shared__ float sm[];
    float* X1T = sm;                 // [128 d][PAD] : X1T[d][i] = x1[i][d]
    float* X2T = sm + 128 * PAD;
    float* S   = sm + 2 * 128 * PAD; // [128 i][PAD j]
    __shared__ float rmax[128], rsum[128], er[128], ecinv[128], w2[128];

    int g = blockIdx.x;
    int tid = threadIdx.x;
    const float* x1g = x1 + (size_t)g * GNODES * DF;
    const float* x2g = x2 + (size_t)g * GNODES * DF;

    for (int idx = tid; idx < GNODES * DF; idx += 256) {
        int i = idx >> 7, d = idx & 127;
        X1T[d * PAD + i] = x1g[idx];
        X2T[d * PAD + i] = x2g[idx];
    }
    __syncthreads();

    int tx = tid & 15, ty = tid >> 4;
    float acc[8][8];
#pragma unroll
    for (int i = 0; i < 8; i++)
#pragma unroll
        for (int j = 0; j < 8; j++) acc[i][j] = 0.f;

    for (int d = 0; d < 128; d++) {
        float ra[8], rb[8];
        *(float4*)&ra[0] = *(const float4*)&X1T[d * PAD + ty * 8];
        *(float4*)&ra[4] = *(const float4*)&X1T[d * PAD + ty * 8 + 4];
        *(float4*)&rb[0] = *(const float4*)&X2T[d * PAD + tx * 8];
        *(float4*)&rb[4] = *(const float4*)&X2T[d * PAD + tx * 8 + 4];
#pragma unroll
        for (int i = 0; i < 8; i++)
#pragma unroll
            for (int j = 0; j < 8; j++) acc[i][j] += ra[i] * rb[j];
    }
#pragma unroll
    for (int i = 0; i < 8; i++) {
        *(float4*)&S[(ty * 8 + i) * PAD + tx * 8]     = *(float4*)&acc[i][0];
        *(float4*)&S[(ty * 8 + i) * PAD + tx * 8 + 4] = *(float4*)&acc[i][4];
    }
    __syncthreads();

    if (tid < 128) {
        int i = tid;
        float m = -1e30f;
        for (int j = 0; j < 128; j++) m = fmaxf(m, S[i * PAD + j]);
        rmax[i] = m;
        er[i] = expf(m);
    } else {
        int j = tid - 128;
        float m = -1e30f;
        for (int i = 0; i < 128; i++) m = fmaxf(m, S[i * PAD + j]);
        ecinv[j] = expf(-m);
    }
    __syncthreads();

    if (tid < 128) {
        int i = tid;
        float m = rmax[i];
        float s = 0.f;
        for (int j = 0; j < 128; j++) {
            float v = expf(S[i * PAD + j] - m);
            S[i * PAD + j] = v;
            s += v;
        }
        rsum[i] = s;
    }
    __syncthreads();

    if (tid >= 128) {
        int j = tid - 128;
        float s = 0.f;
        for (int i = 0; i < 128; i++) s += S[i * PAD + j] * er[i];
        float cs = s * ecinv[j];
        w2[j] = ecinv[j] / cs;
    }
    __syncthreads();

    float* P1g = P1  + (size_t)g * GNODES * GNODES;
    float* P2g = P2T + (size_t)g * GNODES * GNODES;
    for (int idx = tid; idx < GNODES * GNODES; idx += 256) {  // P1[i][j]
        int i = idx >> 7, j = idx & 127;
        P1g[idx] = S[i * PAD + j] / rsum[i];
    }
    for (int idx = tid; idx < GNODES * GNODES; idx += 256) {  // P2T[j][i]
        int j = idx >> 7, i = idx & 127;
        P2g[idx] = S[i * PAD + j] * er[i] * w2[j];
    }
}

// grid=(64,2): z=0 -> att1 = x1 - P1 @ x2 ; z=1 -> att2 = x2 - P2^T @ x1
__global__ void att_apply(const float* __restrict__ x1, const float* __restrict__ x2,
                          const float* __restrict__ P1, const float* __restrict__ P2T) {
    extern __shared__ float sm[];
    float* As = sm;              // [k][PAD m]  (k-major)
    float* Bs = sm + 128 * PAD;  // [k][PAD d]
    int g = blockIdx.x, z = blockIdx.y;
    const float* Ag; const float* Bg; const float* baseg; int rowBase;
    if (z == 0) {
        Ag = P1  + (size_t)g * GNODES * GNODES;
        Bg = x2  + (size_t)g * GNODES * DF;
        baseg = x1 + (size_t)g * GNODES * DF;
        rowBase = g * GNODES;
    } else {
        Ag = P2T + (size_t)g * GNODES * GNODES;
        Bg = x1  + (size_t)g * GNODES * DF;
        baseg = x2 + (size_t)g * GNODES * DF;
        rowBase = NN + g * GNODES;
    }
    int tid = threadIdx.x;
    for (int idx = tid; idx < GNODES * GNODES; idx += 256) {
        int m = idx >> 7, k = idx & 127;
        As[k * PAD + m] = Ag[idx];
        Bs[m * PAD + k] = Bg[idx];
    }
    __syncthreads();

    int tx = tid & 15, ty = tid >> 4;
    float acc[8][8];
#pragma unroll
    for (int i = 0; i < 8; i++)
#pragma unroll
        for (int j = 0; j < 8; j++) acc[i][j] = 0.f;

    for (int k = 0; k < 128; k++) {
        float ra[8], rb[8];
        *(float4*)&ra[0] = *(const float4*)&As[k * PAD + ty * 8];
        *(float4*)&ra[4] = *(const float4*)&As[k * PAD + ty * 8 + 4];
        *(float4*)&rb[0] = *(const float4*)&Bs[k * PAD + tx * 8];
        *(float4*)&rb[4] = *(const float4*)&Bs[k * PAD + tx * 8 + 4];
#pragma unroll
        for (int i = 0; i < 8; i++)
#pragma unroll
            for (int j = 0; j < 8; j++) acc[i][j] += ra[i] * rb[j];
    }

#pragma unroll
    for (int i = 0; i < 8; i++) {
        int m = ty * 8 + i;
#pragma unroll
        for (int j = 0; j < 8; j++) {
            int d = tx * 8 + j;
            float v = baseg[m * DF + d] - acc[i][j];
            g_U[(size_t)(rowBase + m) * 512 + 256 + d] = v;
        }
    }
}

// ---------------- tf32 tensor-core GEMM: C = A@W (+bias*rowscale) (+resid) (relu)
// BM=BN=128, BK=32, 256 threads (8 warps), warp tile 64x32 (4x4 m16n8k8)
// Smem in k-chunked layout [k/4][row][k%4], chunk stride 516 floats:
//  - fragment LDS: bank = (4*chunk + 4*row + kin) mod 32 -> conflict-free
//  - A tile stores conflict-free; B stores <=4-way (once per K-iter)
#define CHS 516
__global__ __launch_bounds__(256, 2)
void sgemm_tc(const float* __restrict__ A, int lda,
              const float* __restrict__ W, int ldw,
              const float* __restrict__ bias,
              const int*   __restrict__ degv,
              const float* __restrict__ resid, int ldr,
              float* __restrict__ C, int ldc,
              int K, int doRelu) {
    __shared__ float As[8 * CHS];
    __shared__ float Bs[8 * CHS];
    const int tid  = threadIdx.x;
    const int lane = tid & 31, warp = tid >> 5;
    const int wM = warp & 1, wN = warp >> 1;     // 2 x 4 warp grid
    const int gidr = lane >> 2, t4 = lane & 3;
    const int brow = blockIdx.y * 128;
    const int bcol = blockIdx.x * 128;

    // loader indices
    const int arow = tid >> 3;        // 0..31
    const int ako  = tid & 7;         // 0..7 (k-chunk)
    const int bn   = tid & 127;       // 0..127 (output col)
    const int bko0 = tid >> 7;        // 0..1

    float acc[4][4][4];
#pragma unroll
    for (int mt = 0; mt < 4; mt++)
#pragma unroll
        for (int nt = 0; nt < 4; nt++)
#pragma unroll
            for (int r = 0; r < 4; r++) acc[mt][nt][r] = 0.f;

    for (int k0 = 0; k0 < K; k0 += 32) {
        __syncthreads();
        // A tile: rows brow..+127, k k0..+31
#pragma unroll
        for (int it = 0; it < 4; it++) {
            int r = arow + 32 * it;
            const float4 v = *(const float4*)(A + (size_t)(brow + r) * lda + k0 + ako * 4);
            float* d = &As[ako * CHS + r * 4];
            d[0] = to_tf32(v.x); d[1] = to_tf32(v.y); d[2] = to_tf32(v.z); d[3] = to_tf32(v.w);
        }
        // W tile: k k0..+31, cols bcol..+127, stored transposed-chunked
#pragma unroll
        for (int it = 0; it < 4; it++) {
            int ko = bko0 + 2 * it;
            const float* wp = W + (size_t)(k0 + ko * 4) * ldw + bcol + bn;
            float4 v;
            v.x = to_tf32(wp[0]);
            v.y = to_tf32(wp[(size_t)ldw]);
            v.z = to_tf32(wp[2 * (size_t)ldw]);
            v.w = to_tf32(wp[3 * (size_t)ldw]);
            *(float4*)&Bs[ko * CHS + bn * 4] = v;
        }
        __syncthreads();

#pragma unroll
        for (int ks = 0; ks < 4; ks++) {
            const int c0 = ks * 2 * CHS, c1 = c0 + CHS;
            uint32_t af[4][4], bf[4][2];
#pragma unroll
            for (int mt = 0; mt < 4; mt++) {
                int rb = wM * 64 + mt * 16 + gidr;
                af[mt][0] = __float_as_uint(As[c0 + rb * 4 + t4]);
                af[mt][1] = __float_as_uint(As[c0 + (rb + 8) * 4 + t4]);
                af[mt][2] = __float_as_uint(As[c1 + rb * 4 + t4]);
                af[mt][3] = __float_as_uint(As[c1 + (rb + 8) * 4 + t4]);
            }
#pragma unroll
            for (int nt = 0; nt < 4; nt++) {
                int cb = wN * 32 + nt * 8 + gidr;
                bf[nt][0] = __float_as_uint(Bs[c0 + cb * 4 + t4]);
                bf[nt][1] = __float_as_uint(Bs[c1 + cb * 4 + t4]);
            }
#pragma unroll
            for (int mt = 0; mt < 4; mt++)
#pragma unroll
                for (int nt = 0; nt < 4; nt++)
                    mma8(acc[mt][nt], af[mt], bf[nt]);
        }
    }

    // epilogue: c0,c1 -> (row=gidr, col=t4*2, +1); c2,c3 -> row+8
#pragma unroll
    for (int mt = 0; mt < 4; mt++) {
#pragma unroll
        for (int half = 0; half < 2; half++) {
            int row = brow + wM * 64 + mt * 16 + gidr + half * 8;
            float rs = degv ? (float)degv[row] : 1.0f;
#pragma unroll
            for (int nt = 0; nt < 4; nt++) {
                int col = bcol + wN * 32 + nt * 8 + t4 * 2;
                float v0 = acc[mt][nt][half * 2 + 0];
                float v1 = acc[mt][nt][half * 2 + 1];
                if (bias)  { v0 += bias[col] * rs;  v1 += bias[col + 1] * rs; }
                if (resid) { v0 += resid[(size_t)row * ldr + col];
                             v1 += resid[(size_t)row * ldr + col + 1]; }
                if (doRelu) { v0 = fmaxf(v0, 0.f); v1 = fmaxf(v1, 0.f); }
                *(float2*)&C[(size_t)row * ldc + col] = make_float2(v0, v1);
            }
        }
    }
}

// ---------------- host ---------------------------------------------------------
extern "C" void kernel_launch(void* const* d_in, const int* in_sizes, int n_in,
                              void* d_out, int out_size) {
    const float* x1  = (const float*)d_in[0];
    const int*   ei1 = (const int*)  d_in[1];
    const float* x2  = (const float*)d_in[3];
    const int*   ei2 = (const int*)  d_in[4];
    const float* mW1 = (const float*)d_in[6];
    const float* mb1 = (const float*)d_in[7];
    const float* mW2 = (const float*)d_in[8];
    const float* mb2 = (const float*)d_in[9];
    const float* uW1 = (const float*)d_in[10];
    const float* ub1 = (const float*)d_in[11];
    const float* uW2 = (const float*)d_in[12];
    const float* ub2 = (const float*)d_in[13];
    const float* uW3 = (const float*)d_in[14];
    const float* ub3 = (const float*)d_in[15];
    float* out = (float*)d_out;

    float *pA, *pC, *pH, *pU, *pH1, *pH2, *pXS, *pP1, *pP2;
    int *pdeg;
    cudaGetSymbolAddress((void**)&pA,  g_A);
    cudaGetSymbolAddress((void**)&pC,  g_Cb);
    cudaGetSymbolAddress((void**)&pH,  g_H);
    cudaGetSymbolAddress((void**)&pU,  g_U);
    cudaGetSymbolAddress((void**)&pH1, g_H1);
    cudaGetSymbolAddress((void**)&pH2, g_H2);
    cudaGetSymbolAddress((void**)&pXS, g_XS);
    cudaGetSymbolAddress((void**)&pP1, g_P1);
    cudaGetSymbolAddress((void**)&pP2, g_P2);
    cudaGetSymbolAddress((void**)&pdeg, g_deg);

    cudaMemsetAsync(pdeg, 0, NT * sizeof(int));

    copy_x_kernel<<<(NT * DF) / 256, 256>>>(x1, x2);

    hist_kernel<<<2 * EE / 256, 256>>>(ei1, ei2);
    scan_kernel<<<1, 1024>>>();
    scatter_kernel<<<2 * EE / 256, 256>>>(ei1, ei2);

    // G1a: A = X @ W1_top   [NT,512] K=128
    sgemm_tc<<<dim3(4, NT / 128), 256>>>(pXS, 128, mW1, 512,
                                         nullptr, nullptr, nullptr, 0,
                                         pA, 512, 128, 0);
    // G1b: C = X @ W1_bot + mb1
    sgemm_tc<<<dim3(4, NT / 128), 256>>>(pXS, 128, mW1 + 128 * 512, 512,
                                         mb1, nullptr, nullptr, 0,
                                         pC, 512, 128, 0);

    edge_acc_kernel<<<NT, 128>>>();

    // G2: U[:,0:256] = H @ mW2 + deg * mb2
    sgemm_tc<<<dim3(2, NT / 128), 256>>>(pH, 512, mW2, 256,
                                         mb2, pdeg, nullptr, 0,
                                         pU, 512, 512, 0);

    // attention
    size_t smA = (size_t)3 * 128 * PAD * sizeof(float);
    cudaFuncSetAttribute(att_scores, cudaFuncAttributeMaxDynamicSharedMemorySize, (int)smA);
    att_scores<<<GB, 256, smA>>>(x1, x2, pP1, pP2);
    size_t smB = (size_t)2 * 128 * PAD * sizeof(float);
    cudaFuncSetAttribute(att_apply, cudaFuncAttributeMaxDynamicSharedMemorySize, (int)smB);
    att_apply<<<dim3(GB, 2), 256, smB>>>(x1, x2, pP1, pP2);

    // update MLP
    sgemm_tc<<<dim3(4, NT / 128), 256>>>(pU, 512, uW1, 512,
                                         ub1, nullptr, nullptr, 0,
                                         pH1, 512, 512, 1);
    sgemm_tc<<<dim3(2, NT / 128), 256>>>(pH1, 512, uW2, 256,
                                         ub2, nullptr, nullptr, 0,
                                         pH2, 256, 512, 1);
    // G5: out = XS + H2 @ uW3 + ub3
    sgemm_tc<<<dim3(1, NT / 128), 256>>>(pH2, 256, uW3, 128,
                                         ub3, nullptr, pXS, 128,
                                         out, 128, 256, 0);
}